// round 5
// baseline (speedup 1.0000x reference)
#include <cuda_runtime.h>
#include <cuda_fp16.h>
#include <cstdint>

#define N_MAX 100000
#define E_MAX 1000000
#define F_IN  64
#define F_HID 64
#define F_OUT 32
#define XPAD  68
#define SCAN_B 512

// ---------------- scratch (device globals; no allocation allowed) ----------------
__device__ int    g_indeg[N_MAX];
__device__ int    g_outdeg[N_MAX];
__device__ int    g_roff[N_MAX];                   // exclusive CSR offsets (by dst)
__device__ int    g_pos[N_MAX];                    // working copy for fill
__device__ int    g_bsum[256];                     // scan block sums
__device__ int    g_esrc[E_MAX];                   // CSR: src per in-edge, binned by dst
__device__ float  g_deg[2 * N_MAX];                // [0..N): norm_src ; [N..2N): norm_dst
__device__ __half g_t1[(size_t)N_MAX * F_HID];     // (x*ns)@W1, fp16
__device__ float  g_h[(size_t)N_MAX * F_HID];      // relu(agg1*nd+b1)*ns  (gemm2 input)
__device__ __half g_t2[(size_t)N_MAX * F_OUT];     // h@W2, fp16

__device__ __forceinline__ uint32_t pack2(float a, float b) {
    __half2 h = __floats2half2_rn(a, b);
    return *(uint32_t*)&h;
}
__device__ __forceinline__ float2 up2(uint32_t u) {
    __half2 h = *(__half2*)&u;
    return __half22float2(h);
}

// ---------------- zero int degree arrays ----------------
__global__ __launch_bounds__(256) void zero_kernel() {
    int i = blockIdx.x * blockDim.x + threadIdx.x;
    if (i < N_MAX) { g_indeg[i] = 0; g_outdeg[i] = 0; }
}

// ---------------- degree count ----------------
__global__ __launch_bounds__(256) void count_kernel(const int* __restrict__ src,
                                                    const int* __restrict__ dst, int e) {
    int i = blockIdx.x * blockDim.x + threadIdx.x;
    if (i < e) {
        atomicAdd(&g_outdeg[src[i]], 1);
        atomicAdd(&g_indeg[dst[i]], 1);
    }
}

// ---------------- scan level 1: per-512-block inclusive scan ----------------
__global__ __launch_bounds__(SCAN_B) void scan1_kernel(int n) {
    __shared__ int s[SCAN_B];
    int tid = threadIdx.x;
    int i = blockIdx.x * SCAN_B + tid;
    int v = (i < n) ? g_indeg[i] : 0;
    s[tid] = v;
    __syncthreads();
    #pragma unroll
    for (int off = 1; off < SCAN_B; off <<= 1) {
        int t = (tid >= off) ? s[tid - off] : 0;
        __syncthreads();
        s[tid] += t;
        __syncthreads();
    }
    if (i < n) g_roff[i] = s[tid];                 // inclusive for now
    if (tid == SCAN_B - 1) g_bsum[blockIdx.x] = s[tid];
}

// ---------------- scan finalize + norms (fused; replaces scan2+scan3+norm) ----
// 256 nodes/block; scan-block index b = blockIdx.x>>1 is constant per block.
__global__ __launch_bounds__(256) void scan3_kernel(int n) {
    __shared__ int sb[256];
    int tid = threadIdx.x;
    int b = blockIdx.x >> 1;                       // which 512-scan-block we're in
    sb[tid] = (tid < b) ? g_bsum[tid] : 0;         // b <= 195 < 256
    __syncthreads();
    #pragma unroll
    for (int off = 128; off > 0; off >>= 1) {
        if (tid < off) sb[tid] += sb[tid + off];
        __syncthreads();
    }
    int prefix = sb[0];

    int i = blockIdx.x * 256 + tid;
    if (i < n) {
        int ind = g_indeg[i];
        int off = g_roff[i] - ind + prefix;        // global exclusive offset
        g_roff[i] = off;
        g_pos[i] = off;
        g_deg[i]         = rsqrtf(fmaxf((float)g_outdeg[i], 1.0f));
        g_deg[N_MAX + i] = rsqrtf(fmaxf((float)ind, 1.0f));
    }
}

// ---------------- CSR fill ----------------
__global__ __launch_bounds__(256) void fill_kernel(const int* __restrict__ src,
                                                   const int* __restrict__ dst, int e) {
    int i = blockIdx.x * blockDim.x + threadIdx.x;
    if (i < e) {
        int p = atomicAdd(&g_pos[dst[i]], 1);
        g_esrc[p] = src[i];
    }
}

// ---------------- GEMM 1: t1 = (x * norm_src) @ W1   (64 -> 64, out fp16) ----
// 256 threads, 256 nodes/block; 4 nodes x 16 cols per thread.
__global__ __launch_bounds__(256, 2) void gemm1_kernel(const float* __restrict__ x,
                                                       const float* __restrict__ W1, int n) {
    __shared__ float sW[64 * 64];            // 16 KB
    extern __shared__ float sX[];            // 256 * 68 * 4 = 69632 B
    int tid = threadIdx.x;
    int nb = blockIdx.x * 256;

    const float4* W4 = (const float4*)W1;
    float4* sW4 = (float4*)sW;
    #pragma unroll
    for (int idx = tid; idx < 64 * 16; idx += 256) sW4[idx] = W4[idx];

    const float4* x4 = (const float4*)x;
    #pragma unroll 4
    for (int idx = tid; idx < 256 * 16; idx += 256) {
        int row = idx >> 4;
        int c = idx & 15;
        int node = nb + row;
        float4 v = make_float4(0.f, 0.f, 0.f, 0.f);
        if (node < n) {
            v = x4[(size_t)node * 16 + c];
            float ns = g_deg[node];
            v.x *= ns; v.y *= ns; v.z *= ns; v.w *= ns;
        }
        *(float4*)&sX[row * XPAD + c * 4] = v;
    }
    __syncthreads();

    int trow = tid >> 2;    // 0..63
    int jq = tid & 3;       // 16-col group
    float4 acc[4][4] = {};

    #pragma unroll 2
    for (int k = 0; k < 64; k++) {
        float a[4];
        #pragma unroll
        for (int i = 0; i < 4; i++) a[i] = sX[(trow + 64 * i) * XPAD + k];
        const float4* wr = (const float4*)&sW[k * 64 + jq * 16];
        float4 w0 = wr[0], w1 = wr[1], w2 = wr[2], w3 = wr[3];
        #pragma unroll
        for (int i = 0; i < 4; i++) {
            acc[i][0].x += a[i] * w0.x; acc[i][0].y += a[i] * w0.y;
            acc[i][0].z += a[i] * w0.z; acc[i][0].w += a[i] * w0.w;
            acc[i][1].x += a[i] * w1.x; acc[i][1].y += a[i] * w1.y;
            acc[i][1].z += a[i] * w1.z; acc[i][1].w += a[i] * w1.w;
            acc[i][2].x += a[i] * w2.x; acc[i][2].y += a[i] * w2.y;
            acc[i][2].z += a[i] * w2.z; acc[i][2].w += a[i] * w2.w;
            acc[i][3].x += a[i] * w3.x; acc[i][3].y += a[i] * w3.y;
            acc[i][3].z += a[i] * w3.z; acc[i][3].w += a[i] * w3.w;
        }
    }

    #pragma unroll
    for (int i = 0; i < 4; i++) {
        int node = nb + trow + 64 * i;
        if (node < n) {
            uint4 o0, o1;
            o0.x = pack2(acc[i][0].x, acc[i][0].y);
            o0.y = pack2(acc[i][0].z, acc[i][0].w);
            o0.z = pack2(acc[i][1].x, acc[i][1].y);
            o0.w = pack2(acc[i][1].z, acc[i][1].w);
            o1.x = pack2(acc[i][2].x, acc[i][2].y);
            o1.y = pack2(acc[i][2].z, acc[i][2].w);
            o1.z = pack2(acc[i][3].x, acc[i][3].y);
            o1.w = pack2(acc[i][3].z, acc[i][3].w);
            uint4* o = (uint4*)&g_t1[(size_t)node * 64 + jq * 16];
            o[0] = o0; o[1] = o1;
        }
    }
}

// ---------------- gather 1: h = relu((sum t1[src]) * nd + b1) * ns ------------
// 8 threads/node (8 fp16 cols each), 32 nodes/block. fp32 accumulation.
__global__ __launch_bounds__(256) void gather1_kernel(const float* __restrict__ b1, int n) {
    int tid = threadIdx.x;
    int node = blockIdx.x * 32 + (tid >> 3);
    if (node >= n) return;
    int c = tid & 7;                         // owns halves [c*8, c*8+8)
    const uint4* t1v = (const uint4*)g_t1;   // 8 halves per uint4; 8 uint4 per row
    int start = g_roff[node];
    int len = g_indeg[node];
    float f[8] = {};
    int j = 0;
    for (; j + 2 <= len; j += 2) {
        int s0 = g_esrc[start + j];
        int s1 = g_esrc[start + j + 1];
        uint4 v0 = t1v[(size_t)s0 * 8 + c];
        uint4 v1 = t1v[(size_t)s1 * 8 + c];
        float2 p;
        p = up2(v0.x); f[0] += p.x; f[1] += p.y;
        p = up2(v0.y); f[2] += p.x; f[3] += p.y;
        p = up2(v0.z); f[4] += p.x; f[5] += p.y;
        p = up2(v0.w); f[6] += p.x; f[7] += p.y;
        p = up2(v1.x); f[0] += p.x; f[1] += p.y;
        p = up2(v1.y); f[2] += p.x; f[3] += p.y;
        p = up2(v1.z); f[4] += p.x; f[5] += p.y;
        p = up2(v1.w); f[6] += p.x; f[7] += p.y;
    }
    if (j < len) {
        int s0 = g_esrc[start + j];
        uint4 v0 = t1v[(size_t)s0 * 8 + c];
        float2 p;
        p = up2(v0.x); f[0] += p.x; f[1] += p.y;
        p = up2(v0.y); f[2] += p.x; f[3] += p.y;
        p = up2(v0.z); f[4] += p.x; f[5] += p.y;
        p = up2(v0.w); f[6] += p.x; f[7] += p.y;
    }
    float nd = g_deg[N_MAX + node];
    float ns = g_deg[node];
    float4 b0 = ((const float4*)b1)[c * 2];
    float4 b1v = ((const float4*)b1)[c * 2 + 1];
    float4 h0, h1;
    h0.x = fmaxf(fmaf(f[0], nd, b0.x), 0.f) * ns;
    h0.y = fmaxf(fmaf(f[1], nd, b0.y), 0.f) * ns;
    h0.z = fmaxf(fmaf(f[2], nd, b0.z), 0.f) * ns;
    h0.w = fmaxf(fmaf(f[3], nd, b0.w), 0.f) * ns;
    h1.x = fmaxf(fmaf(f[4], nd, b1v.x), 0.f) * ns;
    h1.y = fmaxf(fmaf(f[5], nd, b1v.y), 0.f) * ns;
    h1.z = fmaxf(fmaf(f[6], nd, b1v.z), 0.f) * ns;
    h1.w = fmaxf(fmaf(f[7], nd, b1v.w), 0.f) * ns;
    float4* hp = (float4*)&g_h[(size_t)node * 64 + c * 8];
    hp[0] = h0; hp[1] = h1;
}

// ---------------- GEMM 2: t2 = h @ W2   (64 -> 32, out fp16) ------------------
// 256 threads, 256 nodes/block; 4 nodes x 8 cols per thread.
__global__ __launch_bounds__(256, 2) void gemm2_kernel(const float* __restrict__ W2, int n) {
    __shared__ float sW[64 * 32];            // 8 KB
    extern __shared__ float sX[];            // 69632 B
    int tid = threadIdx.x;
    int nb = blockIdx.x * 256;

    const float4* W4 = (const float4*)W2;
    float4* sW4 = (float4*)sW;
    #pragma unroll
    for (int idx = tid; idx < 64 * 8; idx += 256) sW4[idx] = W4[idx];

    const float4* h4 = (const float4*)g_h;
    #pragma unroll 4
    for (int idx = tid; idx < 256 * 16; idx += 256) {
        int row = idx >> 4;
        int c = idx & 15;
        int node = nb + row;
        float4 v = make_float4(0.f, 0.f, 0.f, 0.f);
        if (node < n) v = h4[(size_t)node * 16 + c];
        *(float4*)&sX[row * XPAD + c * 4] = v;
    }
    __syncthreads();

    int trow = tid >> 2;    // 0..63
    int jq = tid & 3;       // 8-col group
    float4 acc[4][2] = {};

    #pragma unroll 4
    for (int k = 0; k < 64; k++) {
        float a[4];
        #pragma unroll
        for (int i = 0; i < 4; i++) a[i] = sX[(trow + 64 * i) * XPAD + k];
        const float4* wr = (const float4*)&sW[k * 32 + jq * 8];
        float4 w0 = wr[0], w1 = wr[1];
        #pragma unroll
        for (int i = 0; i < 4; i++) {
            acc[i][0].x += a[i] * w0.x; acc[i][0].y += a[i] * w0.y;
            acc[i][0].z += a[i] * w0.z; acc[i][0].w += a[i] * w0.w;
            acc[i][1].x += a[i] * w1.x; acc[i][1].y += a[i] * w1.y;
            acc[i][1].z += a[i] * w1.z; acc[i][1].w += a[i] * w1.w;
        }
    }

    #pragma unroll
    for (int i = 0; i < 4; i++) {
        int node = nb + trow + 64 * i;
        if (node < n) {
            uint4 o0;
            o0.x = pack2(acc[i][0].x, acc[i][0].y);
            o0.y = pack2(acc[i][0].z, acc[i][0].w);
            o0.z = pack2(acc[i][1].x, acc[i][1].y);
            o0.w = pack2(acc[i][1].z, acc[i][1].w);
            *(uint4*)&g_t2[(size_t)node * 32 + jq * 8] = o0;
        }
    }
}

// ---------------- gather 2: out = relu((sum t2[src]) * nd + b2) ---------------
// 4 threads/node (8 fp16 cols each), 64 nodes/block.
__global__ __launch_bounds__(256) void gather2_kernel(const float* __restrict__ b2,
                                                      float* __restrict__ out, int n) {
    int tid = threadIdx.x;
    int node = blockIdx.x * 64 + (tid >> 2);
    if (node >= n) return;
    int c = tid & 3;                         // owns halves [c*8, c*8+8)
    const uint4* t2v = (const uint4*)g_t2;   // 4 uint4 per row
    int start = g_roff[node];
    int len = g_indeg[node];
    float f[8] = {};
    int j = 0;
    for (; j + 2 <= len; j += 2) {
        int s0 = g_esrc[start + j];
        int s1 = g_esrc[start + j + 1];
        uint4 v0 = t2v[(size_t)s0 * 4 + c];
        uint4 v1 = t2v[(size_t)s1 * 4 + c];
        float2 p;
        p = up2(v0.x); f[0] += p.x; f[1] += p.y;
        p = up2(v0.y); f[2] += p.x; f[3] += p.y;
        p = up2(v0.z); f[4] += p.x; f[5] += p.y;
        p = up2(v0.w); f[6] += p.x; f[7] += p.y;
        p = up2(v1.x); f[0] += p.x; f[1] += p.y;
        p = up2(v1.y); f[2] += p.x; f[3] += p.y;
        p = up2(v1.z); f[4] += p.x; f[5] += p.y;
        p = up2(v1.w); f[6] += p.x; f[7] += p.y;
    }
    if (j < len) {
        int s0 = g_esrc[start + j];
        uint4 v0 = t2v[(size_t)s0 * 4 + c];
        float2 p;
        p = up2(v0.x); f[0] += p.x; f[1] += p.y;
        p = up2(v0.y); f[2] += p.x; f[3] += p.y;
        p = up2(v0.z); f[4] += p.x; f[5] += p.y;
        p = up2(v0.w); f[6] += p.x; f[7] += p.y;
    }
    float nd = g_deg[N_MAX + node];
    float4 b0 = ((const float4*)b2)[c * 2];
    float4 b1v = ((const float4*)b2)[c * 2 + 1];
    float4 o0, o1;
    o0.x = fmaxf(fmaf(f[0], nd, b0.x), 0.f);
    o0.y = fmaxf(fmaf(f[1], nd, b0.y), 0.f);
    o0.z = fmaxf(fmaf(f[2], nd, b0.z), 0.f);
    o0.w = fmaxf(fmaf(f[3], nd, b0.w), 0.f);
    o1.x = fmaxf(fmaf(f[4], nd, b1v.x), 0.f);
    o1.y = fmaxf(fmaf(f[5], nd, b1v.y), 0.f);
    o1.z = fmaxf(fmaf(f[6], nd, b1v.z), 0.f);
    o1.w = fmaxf(fmaf(f[7], nd, b1v.w), 0.f);
    float4* op = (float4*)&out[(size_t)node * 32 + c * 8];
    op[0] = o0; op[1] = o1;
}

// ---------------- launch ----------------
extern "C" void kernel_launch(void* const* d_in, const int* in_sizes, int n_in,
                              void* d_out, int out_size) {
    const float* x  = (const float*)d_in[0];
    const int*   ei = (const int*)d_in[1];
    const float* W1 = (const float*)d_in[2];
    const float* b1 = (const float*)d_in[3];
    const float* W2 = (const float*)d_in[4];
    const float* b2 = (const float*)d_in[5];
    float* out = (float*)d_out;

    int n = in_sizes[0] / F_IN;     // 100000
    int e = in_sizes[1] / 2;        // 1000000
    const int* src = ei;
    const int* dst = ei + e;

    const int SX_BYTES = 256 * XPAD * 4;    // 69632
    cudaFuncSetAttribute(gemm1_kernel, cudaFuncAttributeMaxDynamicSharedMemorySize, SX_BYTES);
    cudaFuncSetAttribute(gemm2_kernel, cudaFuncAttributeMaxDynamicSharedMemorySize, SX_BYTES);

    int nscan = (n + SCAN_B - 1) / SCAN_B;  // 196

    zero_kernel<<<(N_MAX + 255) / 256, 256>>>();
    count_kernel<<<(e + 255) / 256, 256>>>(src, dst, e);
    scan1_kernel<<<nscan, SCAN_B>>>(n);
    scan3_kernel<<<(n + 255) / 256, 256>>>(n);
    fill_kernel<<<(e + 255) / 256, 256>>>(src, dst, e);

    gemm1_kernel<<<(n + 255) / 256, 256, SX_BYTES>>>(x, W1, n);
    gather1_kernel<<<(n + 31) / 32, 256>>>(b1, n);
    gemm2_kernel<<<(n + 255) / 256, 256, SX_BYTES>>>(W2, n);
    gather2_kernel<<<(n + 63) / 64, 256>>>(b2, out, n);
}

// round 6
// speedup vs baseline: 1.0947x; 1.0947x over previous
#include <cuda_runtime.h>
#include <cuda_fp16.h>
#include <cstdint>

#define N_MAX 100000
#define E_MAX 1000000
#define F_IN  64
#define F_HID 64
#define F_OUT 32
#define XPAD  68
#define SCAN_B 512

// ---------------- scratch (device globals; no allocation allowed) ----------------
__device__ int    g_indeg[N_MAX];
__device__ int    g_outdeg[N_MAX];
__device__ int    g_roff[N_MAX];                   // exclusive CSR offsets (by dst)
__device__ int    g_pos[N_MAX];                    // working copy for fill
__device__ int    g_bsum[256];                     // scan block sums
__device__ int    g_esrc[E_MAX];                   // CSR: src per in-edge, binned by dst
__device__ float  g_deg[2 * N_MAX];                // [0..N): norm_src ; [N..2N): norm_dst
__device__ __half g_t1[(size_t)N_MAX * F_HID];     // x@W1 (UNSCALED), fp16
__device__ float  g_h[(size_t)N_MAX * F_HID];      // relu(agg1*nd+b1)*ns  (gemm2 input)
__device__ __half g_t2[(size_t)N_MAX * F_OUT];     // h@W2, fp16

__device__ __forceinline__ uint32_t pack2(float a, float b) {
    __half2 h = __floats2half2_rn(a, b);
    return *(uint32_t*)&h;
}
__device__ __forceinline__ float2 up2(uint32_t u) {
    __half2 h = *(__half2*)&u;
    return __half22float2(h);
}
// accumulate 8 halves of v into f[0..8) with weight w
__device__ __forceinline__ void accw8(float* f, uint4 v, float w) {
    float2 p;
    p = up2(v.x); f[0] = fmaf(p.x, w, f[0]); f[1] = fmaf(p.y, w, f[1]);
    p = up2(v.y); f[2] = fmaf(p.x, w, f[2]); f[3] = fmaf(p.y, w, f[3]);
    p = up2(v.z); f[4] = fmaf(p.x, w, f[4]); f[5] = fmaf(p.y, w, f[5]);
    p = up2(v.w); f[6] = fmaf(p.x, w, f[6]); f[7] = fmaf(p.y, w, f[7]);
}

// ---------------- degree count ----------------
__global__ __launch_bounds__(256) void count_kernel(const int* __restrict__ src,
                                                    const int* __restrict__ dst, int e) {
    int i = blockIdx.x * blockDim.x + threadIdx.x;
    if (i < e) {
        atomicAdd(&g_outdeg[src[i]], 1);
        atomicAdd(&g_indeg[dst[i]], 1);
    }
}

// ---------------- scan level 1: per-512-block inclusive scan ----------------
__global__ __launch_bounds__(SCAN_B) void scan1_kernel(int n) {
    __shared__ int s[SCAN_B];
    int tid = threadIdx.x;
    int i = blockIdx.x * SCAN_B + tid;
    int v = (i < n) ? g_indeg[i] : 0;
    s[tid] = v;
    __syncthreads();
    #pragma unroll
    for (int off = 1; off < SCAN_B; off <<= 1) {
        int t = (tid >= off) ? s[tid - off] : 0;
        __syncthreads();
        s[tid] += t;
        __syncthreads();
    }
    if (i < n) g_roff[i] = s[tid];                 // inclusive for now
    if (tid == SCAN_B - 1) g_bsum[blockIdx.x] = s[tid];
}

// ---------------- scan finalize + norms (fused) ----------------
__global__ __launch_bounds__(256) void scan3_kernel(int n) {
    __shared__ int sb[256];
    int tid = threadIdx.x;
    int b = blockIdx.x >> 1;                       // which 512-scan-block we're in
    sb[tid] = (tid < b) ? g_bsum[tid] : 0;         // b <= 195 < 256
    __syncthreads();
    #pragma unroll
    for (int off = 128; off > 0; off >>= 1) {
        if (tid < off) sb[tid] += sb[tid + off];
        __syncthreads();
    }
    int prefix = sb[0];

    int i = blockIdx.x * 256 + tid;
    if (i < n) {
        int ind = g_indeg[i];
        int off = g_roff[i] - ind + prefix;        // global exclusive offset
        g_roff[i] = off;
        g_pos[i] = off;
        g_deg[i]         = rsqrtf(fmaxf((float)g_outdeg[i], 1.0f));
        g_deg[N_MAX + i] = rsqrtf(fmaxf((float)ind, 1.0f));
    }
}

// ---------------- CSR fill ----------------
__global__ __launch_bounds__(256) void fill_kernel(const int* __restrict__ src,
                                                   const int* __restrict__ dst, int e) {
    int i = blockIdx.x * blockDim.x + threadIdx.x;
    if (i < e) {
        int p = atomicAdd(&g_pos[dst[i]], 1);
        g_esrc[p] = src[i];
    }
}

// ---------------- GEMM 1: t1 = x @ W1 (UNSCALED, 64 -> 64, out fp16) ----------
// 256 threads, 256 nodes/block; 4 nodes x 16 cols per thread. No g_deg dep.
__global__ __launch_bounds__(256, 2) void gemm1_kernel(const float* __restrict__ x,
                                                       const float* __restrict__ W1, int n) {
    __shared__ float sW[64 * 64];            // 16 KB
    extern __shared__ float sX[];            // 256 * 68 * 4 = 69632 B
    int tid = threadIdx.x;
    int nb = blockIdx.x * 256;

    const float4* W4 = (const float4*)W1;
    float4* sW4 = (float4*)sW;
    #pragma unroll
    for (int idx = tid; idx < 64 * 16; idx += 256) sW4[idx] = W4[idx];

    const float4* x4 = (const float4*)x;
    #pragma unroll 4
    for (int idx = tid; idx < 256 * 16; idx += 256) {
        int row = idx >> 4;
        int c = idx & 15;
        int node = nb + row;
        float4 v = make_float4(0.f, 0.f, 0.f, 0.f);
        if (node < n) v = x4[(size_t)node * 16 + c];
        *(float4*)&sX[row * XPAD + c * 4] = v;
    }
    __syncthreads();

    int trow = tid >> 2;    // 0..63
    int jq = tid & 3;       // 16-col group
    float4 acc[4][4] = {};

    #pragma unroll 2
    for (int k = 0; k < 64; k++) {
        float a[4];
        #pragma unroll
        for (int i = 0; i < 4; i++) a[i] = sX[(trow + 64 * i) * XPAD + k];
        const float4* wr = (const float4*)&sW[k * 64 + jq * 16];
        float4 w0 = wr[0], w1 = wr[1], w2 = wr[2], w3 = wr[3];
        #pragma unroll
        for (int i = 0; i < 4; i++) {
            acc[i][0].x += a[i] * w0.x; acc[i][0].y += a[i] * w0.y;
            acc[i][0].z += a[i] * w0.z; acc[i][0].w += a[i] * w0.w;
            acc[i][1].x += a[i] * w1.x; acc[i][1].y += a[i] * w1.y;
            acc[i][1].z += a[i] * w1.z; acc[i][1].w += a[i] * w1.w;
            acc[i][2].x += a[i] * w2.x; acc[i][2].y += a[i] * w2.y;
            acc[i][2].z += a[i] * w2.z; acc[i][2].w += a[i] * w2.w;
            acc[i][3].x += a[i] * w3.x; acc[i][3].y += a[i] * w3.y;
            acc[i][3].z += a[i] * w3.z; acc[i][3].w += a[i] * w3.w;
        }
    }

    #pragma unroll
    for (int i = 0; i < 4; i++) {
        int node = nb + trow + 64 * i;
        if (node < n) {
            uint4 o0, o1;
            o0.x = pack2(acc[i][0].x, acc[i][0].y);
            o0.y = pack2(acc[i][0].z, acc[i][0].w);
            o0.z = pack2(acc[i][1].x, acc[i][1].y);
            o0.w = pack2(acc[i][1].z, acc[i][1].w);
            o1.x = pack2(acc[i][2].x, acc[i][2].y);
            o1.y = pack2(acc[i][2].z, acc[i][2].w);
            o1.z = pack2(acc[i][3].x, acc[i][3].y);
            o1.w = pack2(acc[i][3].z, acc[i][3].w);
            uint4* o = (uint4*)&g_t1[(size_t)node * 64 + jq * 16];
            o[0] = o0; o[1] = o1;
        }
    }
}

// ---------------- gather 1: h = relu((sum ns[s]*t1[s]) * nd + b1) * ns --------
// 8 threads/node (8 fp16 cols each), 32 nodes/block. Edge batches of 4 -> MLP 4.
__global__ __launch_bounds__(256) void gather1_kernel(const float* __restrict__ b1, int n) {
    int tid = threadIdx.x;
    int node = blockIdx.x * 32 + (tid >> 3);
    if (node >= n) return;
    int c = tid & 7;                         // owns halves [c*8, c*8+8)
    const uint4* t1v = (const uint4*)g_t1;   // 8 uint4 per row
    const int* ep = g_esrc + g_roff[node];
    int len = g_indeg[node];
    float f[8] = {};
    int j = 0;
    for (; j + 4 <= len; j += 4) {
        int s0 = ep[j], s1 = ep[j + 1], s2 = ep[j + 2], s3 = ep[j + 3];
        uint4 v0 = t1v[(size_t)s0 * 8 + c];
        uint4 v1 = t1v[(size_t)s1 * 8 + c];
        uint4 v2 = t1v[(size_t)s2 * 8 + c];
        uint4 v3 = t1v[(size_t)s3 * 8 + c];
        float w0 = g_deg[s0], w1 = g_deg[s1], w2 = g_deg[s2], w3 = g_deg[s3];
        accw8(f, v0, w0); accw8(f, v1, w1); accw8(f, v2, w2); accw8(f, v3, w3);
    }
    for (; j < len; j++) {
        int s0 = ep[j];
        uint4 v0 = t1v[(size_t)s0 * 8 + c];
        accw8(f, v0, g_deg[s0]);
    }
    float nd = g_deg[N_MAX + node];
    float ns = g_deg[node];
    float4 b0 = ((const float4*)b1)[c * 2];
    float4 b1v = ((const float4*)b1)[c * 2 + 1];
    float4 h0, h1;
    h0.x = fmaxf(fmaf(f[0], nd, b0.x), 0.f) * ns;
    h0.y = fmaxf(fmaf(f[1], nd, b0.y), 0.f) * ns;
    h0.z = fmaxf(fmaf(f[2], nd, b0.z), 0.f) * ns;
    h0.w = fmaxf(fmaf(f[3], nd, b0.w), 0.f) * ns;
    h1.x = fmaxf(fmaf(f[4], nd, b1v.x), 0.f) * ns;
    h1.y = fmaxf(fmaf(f[5], nd, b1v.y), 0.f) * ns;
    h1.z = fmaxf(fmaf(f[6], nd, b1v.z), 0.f) * ns;
    h1.w = fmaxf(fmaf(f[7], nd, b1v.w), 0.f) * ns;
    float4* hp = (float4*)&g_h[(size_t)node * 64 + c * 8];
    hp[0] = h0; hp[1] = h1;
}

// ---------------- GEMM 2: t2 = h @ W2   (64 -> 32, out fp16) ------------------
__global__ __launch_bounds__(256, 2) void gemm2_kernel(const float* __restrict__ W2, int n) {
    __shared__ float sW[64 * 32];            // 8 KB
    extern __shared__ float sX[];            // 69632 B
    int tid = threadIdx.x;
    int nb = blockIdx.x * 256;

    const float4* W4 = (const float4*)W2;
    float4* sW4 = (float4*)sW;
    #pragma unroll
    for (int idx = tid; idx < 64 * 8; idx += 256) sW4[idx] = W4[idx];

    const float4* h4 = (const float4*)g_h;
    #pragma unroll 4
    for (int idx = tid; idx < 256 * 16; idx += 256) {
        int row = idx >> 4;
        int c = idx & 15;
        int node = nb + row;
        float4 v = make_float4(0.f, 0.f, 0.f, 0.f);
        if (node < n) v = h4[(size_t)node * 16 + c];
        *(float4*)&sX[row * XPAD + c * 4] = v;
    }
    __syncthreads();

    int trow = tid >> 2;    // 0..63
    int jq = tid & 3;       // 8-col group
    float4 acc[4][2] = {};

    #pragma unroll 4
    for (int k = 0; k < 64; k++) {
        float a[4];
        #pragma unroll
        for (int i = 0; i < 4; i++) a[i] = sX[(trow + 64 * i) * XPAD + k];
        const float4* wr = (const float4*)&sW[k * 32 + jq * 8];
        float4 w0 = wr[0], w1 = wr[1];
        #pragma unroll
        for (int i = 0; i < 4; i++) {
            acc[i][0].x += a[i] * w0.x; acc[i][0].y += a[i] * w0.y;
            acc[i][0].z += a[i] * w0.z; acc[i][0].w += a[i] * w0.w;
            acc[i][1].x += a[i] * w1.x; acc[i][1].y += a[i] * w1.y;
            acc[i][1].z += a[i] * w1.z; acc[i][1].w += a[i] * w1.w;
        }
    }

    #pragma unroll
    for (int i = 0; i < 4; i++) {
        int node = nb + trow + 64 * i;
        if (node < n) {
            uint4 o0;
            o0.x = pack2(acc[i][0].x, acc[i][0].y);
            o0.y = pack2(acc[i][0].z, acc[i][0].w);
            o0.z = pack2(acc[i][1].x, acc[i][1].y);
            o0.w = pack2(acc[i][1].z, acc[i][1].w);
            *(uint4*)&g_t2[(size_t)node * 32 + jq * 8] = o0;
        }
    }
}

// ---------------- gather 2: out = relu((sum t2[src]) * nd + b2) ---------------
// 4 threads/node (8 fp16 cols each), 64 nodes/block. Edge batches of 4.
__global__ __launch_bounds__(256) void gather2_kernel(const float* __restrict__ b2,
                                                      float* __restrict__ out, int n) {
    int tid = threadIdx.x;
    int node = blockIdx.x * 64 + (tid >> 2);
    if (node >= n) return;
    int c = tid & 3;                         // owns halves [c*8, c*8+8)
    const uint4* t2v = (const uint4*)g_t2;   // 4 uint4 per row
    const int* ep = g_esrc + g_roff[node];
    int len = g_indeg[node];
    float f[8] = {};
    int j = 0;
    for (; j + 4 <= len; j += 4) {
        int s0 = ep[j], s1 = ep[j + 1], s2 = ep[j + 2], s3 = ep[j + 3];
        uint4 v0 = t2v[(size_t)s0 * 4 + c];
        uint4 v1 = t2v[(size_t)s1 * 4 + c];
        uint4 v2 = t2v[(size_t)s2 * 4 + c];
        uint4 v3 = t2v[(size_t)s3 * 4 + c];
        accw8(f, v0, 1.f); accw8(f, v1, 1.f); accw8(f, v2, 1.f); accw8(f, v3, 1.f);
    }
    for (; j < len; j++) {
        int s0 = ep[j];
        uint4 v0 = t2v[(size_t)s0 * 4 + c];
        accw8(f, v0, 1.f);
    }
    float nd = g_deg[N_MAX + node];
    float4 b0 = ((const float4*)b2)[c * 2];
    float4 b1v = ((const float4*)b2)[c * 2 + 1];
    float4 o0, o1;
    o0.x = fmaxf(fmaf(f[0], nd, b0.x), 0.f);
    o0.y = fmaxf(fmaf(f[1], nd, b0.y), 0.f);
    o0.z = fmaxf(fmaf(f[2], nd, b0.z), 0.f);
    o0.w = fmaxf(fmaf(f[3], nd, b0.w), 0.f);
    o1.x = fmaxf(fmaf(f[4], nd, b1v.x), 0.f);
    o1.y = fmaxf(fmaf(f[5], nd, b1v.y), 0.f);
    o1.z = fmaxf(fmaf(f[6], nd, b1v.z), 0.f);
    o1.w = fmaxf(fmaf(f[7], nd, b1v.w), 0.f);
    float4* op = (float4*)&out[(size_t)node * 32 + c * 8];
    op[0] = o0; op[1] = o1;
}

// ---------------- launch ----------------
extern "C" void kernel_launch(void* const* d_in, const int* in_sizes, int n_in,
                              void* d_out, int out_size) {
    const float* x  = (const float*)d_in[0];
    const int*   ei = (const int*)d_in[1];
    const float* W1 = (const float*)d_in[2];
    const float* b1 = (const float*)d_in[3];
    const float* W2 = (const float*)d_in[4];
    const float* b2 = (const float*)d_in[5];
    float* out = (float*)d_out;

    int n = in_sizes[0] / F_IN;     // 100000
    int e = in_sizes[1] / 2;        // 1000000
    const int* src = ei;
    const int* dst = ei + e;

    // one-time stream/event setup (first call is the non-captured correctness run)
    static cudaStream_t s2 = nullptr;
    static cudaEvent_t evFork = nullptr, evJoin = nullptr;
    if (s2 == nullptr) {
        cudaStreamCreateWithFlags(&s2, cudaStreamNonBlocking);
        cudaEventCreateWithFlags(&evFork, cudaEventDisableTiming);
        cudaEventCreateWithFlags(&evJoin, cudaEventDisableTiming);
    }

    const int SX_BYTES = 256 * XPAD * 4;    // 69632
    cudaFuncSetAttribute(gemm1_kernel, cudaFuncAttributeMaxDynamicSharedMemorySize, SX_BYTES);
    cudaFuncSetAttribute(gemm2_kernel, cudaFuncAttributeMaxDynamicSharedMemorySize, SX_BYTES);

    int nscan = (n + SCAN_B - 1) / SCAN_B;  // 196

    // fork: gemm1 (no CSR dependency) on side stream
    cudaEventRecord(evFork, 0);
    cudaStreamWaitEvent(s2, evFork, 0);
    gemm1_kernel<<<(n + 255) / 256, 256, SX_BYTES, s2>>>(x, W1, n);
    cudaEventRecord(evJoin, s2);

    // main stream: CSR build chain
    int* degbase;
    cudaGetSymbolAddress((void**)&degbase, g_indeg);
    cudaMemsetAsync(degbase, 0, N_MAX * sizeof(int));
    cudaGetSymbolAddress((void**)&degbase, g_outdeg);
    cudaMemsetAsync(degbase, 0, N_MAX * sizeof(int));
    count_kernel<<<(e + 255) / 256, 256>>>(src, dst, e);
    scan1_kernel<<<nscan, SCAN_B>>>(n);
    scan3_kernel<<<(n + 255) / 256, 256>>>(n);
    fill_kernel<<<(e + 255) / 256, 256>>>(src, dst, e);

    // join: gather1 needs both CSR and t1
    cudaStreamWaitEvent(0, evJoin, 0);
    gather1_kernel<<<(n + 31) / 32, 256>>>(b1, n);
    gemm2_kernel<<<(n + 255) / 256, 256, SX_BYTES>>>(W2, n);
    gather2_kernel<<<(n + 63) / 64, 256>>>(b2, out, n);
}